// round 9
// baseline (speedup 1.0000x reference)
#include <cuda_runtime.h>
#include <cuda_bf16.h>
#include <cstdint>

// Problem constants
#define U_ROWS 50000
#define N_ITEMS 4000
#define BATCH 256
#define MAXK 64
#define CAND 32                 // approx candidates per row, rescored exactly

// GEMM config: CTA tile 128(M) x 256(N), BK=32 (s8), 3-stage ring,
// 8 warps 2(M) x 4(N), warp tile 64x64, IMMA m16n8k32.
#define BK 32
#define KITERS (N_ITEMS / BK)   // 125
#define NTHREADS 256

#define STAGE_BYTES 12288       // A s8 128x32B (4K) + B s8 256x32B (8K)
#define OFF_INVNA (3 * STAGE_BYTES)        // 36864
#define OFF_SXA   (OFF_INVNA + 512)
#define OFF_INVNU (OFF_SXA + 512)
#define OFF_SYB   (OFF_INVNU + 1024)
#define SMEM_TOTAL (OFF_SYB + 1024 + 64)

#define INV_Q2 (1.0f / 16129.0f)   // 1/127^2

// ---------------- scratch (static device memory) ---------------------------
__device__ __align__(16) float g_sim[(size_t)BATCH * U_ROWS];      // 51.2 MB [b][u]
__device__ __align__(16) float g_users[(size_t)BATCH * N_ITEMS];   // 4 MB fp32
__device__ __align__(16) int8_t g_users_q[(size_t)BATCH * N_ITEMS];// 1 MB s8
__device__ float g_inv_na[U_ROWS];
__device__ float g_inv_nu[BATCH];
__device__ float g_sum_u[BATCH];       // Sy = sum of user row
__device__ float g_cval2[BATCH * 2 * CAND];
__device__ int   g_cidx2[BATCH * 2 * CAND];
__device__ int   g_cand_idx[BATCH * CAND];
__device__ float g_nb_val[BATCH * MAXK];
__device__ int   g_nb_idx[BATCH * MAXK];
__device__ int   g_k;
__device__ int   g_is64;

// ---------------- helpers ---------------------------------------------------
__device__ __forceinline__ uint32_t smem_u32(const void* p) {
    uint32_t a;
    asm("{ .reg .u64 t; cvta.to.shared.u64 t, %1; cvt.u32.u64 %0, t; }" : "=r"(a) : "l"(p));
    return a;
}
#define CP_ASYNC16(dst, src) \
    asm volatile("cp.async.cg.shared.global [%0], [%1], 16;" :: "r"(dst), "l"(src))
#define CP_COMMIT() asm volatile("cp.async.commit_group;" ::: "memory")
#define CP_WAIT(n)  asm volatile("cp.async.wait_group %0;" :: "n"(n) : "memory")

__device__ __forceinline__ float neg_inf() { return __int_as_float(0xFF800000); }
// q = round(254x - 127), saturated pack of 4 s32 -> s8x4 (little endian)
__device__ __forceinline__ int quant(float x) {
    return __float2int_rn(fmaf(x, 254.f, -127.f));
}
__device__ __forceinline__ uint32_t pack4_s8(int q0, int q1, int q2, int q3) {
    uint32_t t, d;
    asm("cvt.pack.sat.s8.s32.b32 %0, %1, %2, 0;" : "=r"(t) : "r"(q3), "r"(q2));
    asm("cvt.pack.sat.s8.s32.b32 %0, %1, %2, %3;" : "=r"(d) : "r"(q1), "r"(q0), "r"(t));
    return d;
}
// order-preserving composite key: (value desc, index asc)
__device__ __forceinline__ unsigned long long okey(float v, int idx) {
    unsigned kb = __float_as_uint(v);
    kb ^= (kb >> 31) ? 0xFFFFFFFFu : 0x80000000u;
    return ((unsigned long long)kb << 32) |
           (unsigned long long)(0xFFFFFFFFu - (unsigned)idx);
}

// ---------------- kernel 0: dtype/mode + k detection ------------------------
__global__ void mode_kernel(const void* ids, const int* kptr, int has_k) {
    if (threadIdx.x == 0) {
        const unsigned* w = (const unsigned*)ids;
        bool is64 = true;
        for (int i = 0; i < 16; i++)
            if (w[2 * i + 1] != 0u) { is64 = false; break; }
        g_is64 = is64 ? 1 : 0;

        int kk = 10;
        if (has_k) {
            int vi = kptr[0];
            if (vi >= 1 && vi <= MAXK) kk = vi;
            else {
                float vf = __int_as_float(vi);
                if (vf >= 1.f && vf <= (float)MAXK) kk = (int)vf;
            }
        }
        g_k = kk;
    }
}

// ---------------- kernel 1: gather user rows (fp32 + s8) + norms + sums -----
__global__ void gather_users_kernel(const float* __restrict__ F, const void* ids) {
    const int b = blockIdx.x;
    const int tid = threadIdx.x;
    long long uid;
    if (g_is64) uid = ((const long long*)ids)[b];
    else        uid = (long long)((const int*)ids)[b];
    const float4* src = (const float4*)(F + (size_t)uid * N_ITEMS);
    float4* dstf = (float4*)(g_users + (size_t)b * N_ITEMS);
    uint32_t* dstq = (uint32_t*)(g_users_q + (size_t)b * N_ITEMS);
    float s = 0.f, sy = 0.f;
    for (int v = tid; v < N_ITEMS / 4; v += 256) {
        float4 x = src[v];
        dstf[v] = x;
        dstq[v] = pack4_s8(quant(x.x), quant(x.y), quant(x.z), quant(x.w));
        s += x.x * x.x + x.y * x.y + x.z * x.z + x.w * x.w;
        sy += x.x + x.y + x.z + x.w;
    }
    for (int off = 16; off > 0; off >>= 1) {
        s  += __shfl_down_sync(0xFFFFFFFFu, s, off);
        sy += __shfl_down_sync(0xFFFFFFFFu, sy, off);
    }
    __shared__ float ws[8], wy[8];
    if ((tid & 31) == 0) { ws[tid >> 5] = s; wy[tid >> 5] = sy; }
    __syncthreads();
    if (tid == 0) {
        float t = 0.f, ty = 0.f;
        for (int i = 0; i < 8; i++) { t += ws[i]; ty += wy[i]; }
        g_inv_nu[b] = 1.0f / fmaxf(t, 1e-8f);
        g_sum_u[b] = ty;
    }
}

// ---------------- kernel 2: s8 IMMA GEMM (128x256, warp 64x64) --------------
__global__ __launch_bounds__(NTHREADS, 1)
void gemm_sim_kernel(const float* __restrict__ F) {
    extern __shared__ __align__(1024) char smem[];
    const uint32_t sbase = smem_u32(smem);
    const int tid = threadIdx.x;
    const int lane = tid & 31;
    const int wid = tid >> 5;
    const int m0 = blockIdx.x * 128;
    const int mw = wid & 1;       // warp M index (0..1)
    const int nw = wid >> 1;      // warp N index (0..3)

    float* invna_s = (float*)(smem + OFF_INVNA);
    float* sxa_s   = (float*)(smem + OFF_SXA);
    float* invnu_s = (float*)(smem + OFF_INVNU);
    float* syb_s   = (float*)(smem + OFF_SYB);
    invnu_s[tid] = g_inv_nu[tid];
    syb_s[tid]   = 2.0f * g_sum_u[tid];

    // ---- A producer: thread owns (row, 16B s8 chunk) = 64B fp32 ----
    const int arow = tid >> 1;            // 0..127
    const int ach = tid & 1;              // 16B s8 chunk = 16 fp32
    int gm = m0 + arow; if (gm > U_ROWS - 1) gm = U_ROWS - 1;
    const char* asrc = (const char*)F + (size_t)gm * (N_ITEMS * 4) + ach * 64;
    const uint32_t asts = (uint32_t)(arow * 32 + 16 * (ach ^ ((arow >> 2) & 1)));

    // ---- B producer: 512 chunks of 16B over 256 threads (2 each) ----
    const char* bsrc[2];
    uint32_t bst[2];
#pragma unroll
    for (int i = 0; i < 2; i++) {
        int e = tid + 256 * i;
        int row = e >> 1, ch = e & 1;
        bsrc[i] = (const char*)g_users_q + (size_t)row * N_ITEMS + ch * 16;
        bst[i] = (uint32_t)(4096 + row * 32 + 16 * (ch ^ ((row >> 2) & 1)));
    }

    // ---- ldmatrix per-lane address constants ----
    const int mi = lane >> 3;
    const int lswz = (lane >> 2) & 1;     // bit2 of (lane&7) == row bit2
    // A: m0/m1 = rows 0-7/8-15 chunk0; m2/m3 = rows 0-7/8-15 chunk1
    uint32_t a_off[4];
#pragma unroll
    for (int f = 0; f < 4; f++) {
        int row = mw * 64 + f * 16 + (mi & 1) * 8 + (lane & 7);
        int ch = mi >> 1;
        a_off[f] = (uint32_t)(row * 32 + 16 * (ch ^ lswz));
    }
    // B: m0/m1 = rows p..p+7 chunk0/1; m2/m3 = rows p+8..p+15 chunk0/1
    uint32_t b_off[4];
#pragma unroll
    for (int gp = 0; gp < 4; gp++) {
        int nrow = nw * 64 + gp * 16 + (mi >> 1) * 8 + (lane & 7);
        int ch = mi & 1;
        b_off[gp] = (uint32_t)(4096 + nrow * 32 + 16 * (ch ^ lswz));
    }

    int c[4][8][4];
#pragma unroll
    for (int f = 0; f < 4; f++)
#pragma unroll
        for (int g = 0; g < 8; g++)
#pragma unroll
            for (int i = 0; i < 4; i++) c[f][g][i] = 0;

    float ns = 0.f, sx = 0.f;
    float4 av0, av1, av2, av3;

    auto ldgA = [&](int kt) {
        const char* p = asrc + (size_t)kt * (BK * 4);
        av0 = *(const float4*)p;
        av1 = *(const float4*)(p + 16);
        av2 = *(const float4*)(p + 32);
        av3 = *(const float4*)(p + 48);
    };
    auto stsA = [&](uint32_t stagebase) {
        ns += av0.x * av0.x + av0.y * av0.y + av0.z * av0.z + av0.w * av0.w;
        ns += av1.x * av1.x + av1.y * av1.y + av1.z * av1.z + av1.w * av1.w;
        ns += av2.x * av2.x + av2.y * av2.y + av2.z * av2.z + av2.w * av2.w;
        ns += av3.x * av3.x + av3.y * av3.y + av3.z * av3.z + av3.w * av3.w;
        sx += av0.x + av0.y + av0.z + av0.w + av1.x + av1.y + av1.z + av1.w;
        sx += av2.x + av2.y + av2.z + av2.w + av3.x + av3.y + av3.z + av3.w;
        uint32_t p0 = pack4_s8(quant(av0.x), quant(av0.y), quant(av0.z), quant(av0.w));
        uint32_t p1 = pack4_s8(quant(av1.x), quant(av1.y), quant(av1.z), quant(av1.w));
        uint32_t p2 = pack4_s8(quant(av2.x), quant(av2.y), quant(av2.z), quant(av2.w));
        uint32_t p3 = pack4_s8(quant(av3.x), quant(av3.y), quant(av3.z), quant(av3.w));
        asm volatile("st.shared.v4.b32 [%0], {%1,%2,%3,%4};"
                     :: "r"(stagebase + asts), "r"(p0), "r"(p1), "r"(p2), "r"(p3)
                     : "memory");
    };
    auto issueB = [&](int kt) {
        uint32_t stb = sbase + (kt % 3) * STAGE_BYTES;
        size_t koff = (size_t)kt * BK;
        CP_ASYNC16(stb + bst[0], bsrc[0] + koff);
        CP_ASYNC16(stb + bst[1], bsrc[1] + koff);
    };

    // ---- prologue ----
    issueB(0); CP_COMMIT();
    issueB(1); CP_COMMIT();
    ldgA(0);
    stsA(sbase);
    ldgA(1);

    // ---- mainloop ----
    for (int kt = 0; kt < KITERS; ++kt) {
        CP_WAIT(1);
        __syncthreads();
        if (kt + 2 < KITERS) issueB(kt + 2);
        CP_COMMIT();
        if (kt + 1 < KITERS) stsA(sbase + ((kt + 1) % 3) * STAGE_BYTES);
        if (kt + 2 < KITERS) ldgA(kt + 2);

        const uint32_t stb = sbase + (kt % 3) * STAGE_BYTES;

        uint32_t af[4][4];
#pragma unroll
        for (int f = 0; f < 4; ++f) {
            asm volatile("ldmatrix.sync.aligned.m8n8.x4.shared.b16 {%0,%1,%2,%3}, [%4];"
                         : "=r"(af[f][0]), "=r"(af[f][1]), "=r"(af[f][2]), "=r"(af[f][3])
                         : "r"(stb + a_off[f]));
        }
#pragma unroll
        for (int gp = 0; gp < 4; ++gp) {
            uint32_t b0, b1, b2, b3;
            asm volatile("ldmatrix.sync.aligned.m8n8.x4.shared.b16 {%0,%1,%2,%3}, [%4];"
                         : "=r"(b0), "=r"(b1), "=r"(b2), "=r"(b3)
                         : "r"(stb + b_off[gp]));
#pragma unroll
            for (int f = 0; f < 4; ++f) {
                asm volatile(
                    "mma.sync.aligned.m16n8k32.row.col.s32.s8.s8.s32 "
                    "{%0,%1,%2,%3}, {%4,%5,%6,%7}, {%8,%9}, {%0,%1,%2,%3};"
                    : "+r"(c[f][2 * gp][0]), "+r"(c[f][2 * gp][1]),
                      "+r"(c[f][2 * gp][2]), "+r"(c[f][2 * gp][3])
                    : "r"(af[f][0]), "r"(af[f][1]), "r"(af[f][2]), "r"(af[f][3]),
                      "r"(b0), "r"(b1));
                asm volatile(
                    "mma.sync.aligned.m16n8k32.row.col.s32.s8.s8.s32 "
                    "{%0,%1,%2,%3}, {%4,%5,%6,%7}, {%8,%9}, {%0,%1,%2,%3};"
                    : "+r"(c[f][2 * gp + 1][0]), "+r"(c[f][2 * gp + 1][1]),
                      "+r"(c[f][2 * gp + 1][2]), "+r"(c[f][2 * gp + 1][3])
                    : "r"(af[f][0]), "r"(af[f][1]), "r"(af[f][2]), "r"(af[f][3]),
                      "r"(b2), "r"(b3));
            }
        }
    }

    // ---- exact row norms + sums: reduce over the 2 threads sharing a row ----
    {
        float v = ns + __shfl_xor_sync(0xFFFFFFFFu, ns, 1);
        float u = sx + __shfl_xor_sync(0xFFFFFFFFu, sx, 1);
        if ((tid & 1) == 0) {
            float inv = 1.0f / fmaxf(v, 1e-8f);
            invna_s[arow] = 0.25f * inv;              // fold the 1/4 here
            sxa_s[arow] = 2.0f * u - (float)N_ITEMS;  // row term
            if (m0 + arow < U_ROWS) g_inv_na[m0 + arow] = inv;
        }
    }
    __syncthreads();

    // ---- epilogue: reconstruct + scale + direct b-major stores ----
#pragma unroll
    for (int f = 0; f < 4; ++f) {
        int r0 = mw * 64 + f * 16 + (lane >> 2);
        float na0 = invna_s[r0],  rc0 = sxa_s[r0];
        float na8 = invna_s[r0 + 8], rc8 = sxa_s[r0 + 8];
        int u0 = m0 + r0;
        bool ok0 = u0 < U_ROWS;
        bool ok8 = (u0 + 8) < U_ROWS;
#pragma unroll
        for (int g = 0; g < 8; ++g) {
            int col = nw * 64 + g * 8 + 2 * (lane & 3);
            float cy0 = syb_s[col], cy1 = syb_s[col + 1];
            float nu0 = invnu_s[col], nu1 = invnu_s[col + 1];
            float* d0 = g_sim + (size_t)col * U_ROWS + u0;
            float* d1 = d0 + (size_t)U_ROWS;
            if (ok0) {
                d0[0] = (fmaf((float)c[f][g][0], INV_Q2, rc0 + cy0)) * na0 * nu0;
                d1[0] = (fmaf((float)c[f][g][1], INV_Q2, rc0 + cy1)) * na0 * nu1;
            }
            if (ok8) {
                d0[8] = (fmaf((float)c[f][g][2], INV_Q2, rc8 + cy0)) * na8 * nu0;
                d1[8] = (fmaf((float)c[f][g][3], INV_Q2, rc8 + cy1)) * na8 * nu1;
            }
        }
    }
}

// ---------------- kernel 3: approx top-CAND per row HALF --------------------
#define LOCK 8
#define HALF_U (U_ROWS / 2)     // 25000
__global__ void topk_cand_kernel() {
    const int b = blockIdx.x >> 1;
    const int half = blockIdx.x & 1;
    const int tid = threadIdx.x;
    const int lane = tid & 31;
    const int wid = tid >> 5;
    const int base = half * HALF_U;

    float lv[LOCK];
    int   li[LOCK];
#pragma unroll
    for (int j = 0; j < LOCK; j++) { lv[j] = neg_inf(); li[j] = 0x7FFFFFFF; }

    auto push = [&](float v, int u) {
        if (v > lv[LOCK - 1]) {
            float cv = v; int ci = u;
#pragma unroll
            for (int j = 0; j < LOCK; j++) {
                if (cv > lv[j]) {
                    float tv = lv[j]; int ti = li[j];
                    lv[j] = cv; li[j] = ci;
                    cv = tv; ci = ti;
                }
            }
        }
    };

    const float4* row4 = (const float4*)(g_sim + (size_t)b * U_ROWS + base);
    for (int v = tid; v < HALF_U / 4; v += 256) {
        float4 x = row4[v];
        float m = fmaxf(fmaxf(x.x, x.y), fmaxf(x.z, x.w));
        if (m > lv[LOCK - 1]) {
            int u = base + 4 * v;
            push(x.x, u); push(x.y, u + 1); push(x.z, u + 2); push(x.w, u + 3);
        }
    }

    __shared__ unsigned long long wbest[8];
    __shared__ int wtid[8];
    __shared__ int swin;

    for (int r = 0; r < CAND; ++r) {
        unsigned long long best = okey(lv[0], li[0]);
        int bt = tid;
#pragma unroll
        for (int o = 16; o > 0; o >>= 1) {
            unsigned long long ob = __shfl_down_sync(0xFFFFFFFFu, best, o);
            int ot = __shfl_down_sync(0xFFFFFFFFu, bt, o);
            if (ob > best) { best = ob; bt = ot; }
        }
        if (lane == 0) { wbest[wid] = best; wtid[wid] = bt; }
        __syncthreads();
        if (tid == 0) {
            unsigned long long m = wbest[0]; int mt = wtid[0];
            for (int i = 1; i < 8; i++)
                if (wbest[i] > m) { m = wbest[i]; mt = wtid[i]; }
            swin = mt;
        }
        __syncthreads();
        if (tid == swin) {
            g_cval2[blockIdx.x * CAND + r] = lv[0];
            g_cidx2[blockIdx.x * CAND + r] = li[0];
#pragma unroll
            for (int j = 0; j < LOCK - 1; j++) { lv[j] = lv[j + 1]; li[j] = li[j + 1]; }
            lv[LOCK - 1] = neg_inf(); li[LOCK - 1] = 0x7FFFFFFF;
        }
        __syncthreads();
    }
}

// ---------------- kernel 3b: merge the two per-half candidate lists ---------
__global__ void merge_cand_kernel() {
    const int b = blockIdx.x * blockDim.x + threadIdx.x;
    if (b >= BATCH) return;
    const float* v0 = g_cval2 + (2 * b) * CAND;
    const int*   i0 = g_cidx2 + (2 * b) * CAND;
    const float* v1 = g_cval2 + (2 * b + 1) * CAND;
    const int*   i1 = g_cidx2 + (2 * b + 1) * CAND;
    int p = 0, q = 0;
    for (int r = 0; r < CAND; ++r) {
        bool take0;
        if (p >= CAND) take0 = false;
        else if (q >= CAND) take0 = true;
        else take0 = okey(v0[p], i0[p]) > okey(v1[q], i1[q]);
        g_cand_idx[b * CAND + r] = take0 ? i0[p++] : i1[q++];
    }
}

// ---------------- kernel 4: exact fp32 rescore + top-k ----------------------
__global__ void rescore_kernel(const float* __restrict__ F) {
    const int b = blockIdx.x;
    const int tid = threadIdx.x;
    const int lane = tid & 31;
    const int w = tid >> 5;

    __shared__ float ssim[CAND];
    __shared__ int   sidx[CAND];

    const float* ub = g_users + (size_t)b * N_ITEMS;
    for (int cc = w; cc < CAND; cc += 8) {
        int u = g_cand_idx[b * CAND + cc];
        const float* fu = F + (size_t)u * N_ITEMS;
        float acc = 0.f;
        for (int k = lane; k < N_ITEMS; k += 32)
            acc += ub[k] * fu[k];
        for (int o = 16; o > 0; o >>= 1)
            acc += __shfl_down_sync(0xFFFFFFFFu, acc, o);
        if (lane == 0) {
            ssim[cc] = acc * g_inv_na[u] * g_inv_nu[b];
            sidx[cc] = u;
        }
    }
    __syncthreads();

    if (tid == 0) {
        int k = g_k < CAND ? g_k : CAND;
        bool used[CAND];
        for (int i = 0; i < CAND; i++) used[i] = false;
        for (int r = 0; r < k; r++) {
            int bi = -1;
            float bv = neg_inf();
            int bidx = 0x7FFFFFFF;
            for (int cc = 0; cc < CAND; cc++) {
                if (used[cc]) continue;
                float v = ssim[cc];
                if (v > bv || (v == bv && sidx[cc] < bidx)) {
                    bv = v; bidx = sidx[cc]; bi = cc;
                }
            }
            used[bi] = true;
            g_nb_val[b * MAXK + r] = bv;
            g_nb_idx[b * MAXK + r] = bidx;
        }
    }
}

// ---------------- kernel 5: weighted neighbor gather ------------------------
__global__ void ratings_kernel(const float* __restrict__ F, float* __restrict__ out) {
    const int b = blockIdx.x;
    const int tid = threadIdx.x;
    const int k = g_k < CAND ? g_k : CAND;

    __shared__ float w[MAXK];
    __shared__ int   id[MAXK];
    if (tid == 0) {
        float s = 0.f;
        for (int j = 0; j < k; j++) s += g_nb_val[b * MAXK + j];
        float inv = 1.0f / s;
        for (int j = 0; j < k; j++) {
            w[j]  = g_nb_val[b * MAXK + j] * inv;
            id[j] = g_nb_idx[b * MAXK + j];
        }
    }
    __syncthreads();

    for (int i = tid; i < N_ITEMS; i += 256) {
        float acc = 0.f;
        for (int j = 0; j < k; j++)
            acc += w[j] * F[(size_t)id[j] * N_ITEMS + i];
        out[(size_t)b * N_ITEMS + i] = acc;
    }
}

// ---------------- launch ----------------------------------------------------
extern "C" void kernel_launch(void* const* d_in, const int* in_sizes, int n_in,
                              void* d_out, int out_size) {
    const float* F = (const float*)d_in[0];
    const void* ids = d_in[1];
    const int* kptr = (n_in > 2) ? (const int*)d_in[2] : nullptr;

    cudaFuncSetAttribute(gemm_sim_kernel,
                         cudaFuncAttributeMaxDynamicSharedMemorySize, SMEM_TOTAL);

    mode_kernel<<<1, 32>>>(ids, kptr, kptr != nullptr ? 1 : 0);
    gather_users_kernel<<<BATCH, 256>>>(F, ids);

    int grid = (U_ROWS + 127) / 128;   // 391
    gemm_sim_kernel<<<grid, NTHREADS, SMEM_TOTAL>>>(F);

    topk_cand_kernel<<<2 * BATCH, 256>>>();
    merge_cand_kernel<<<(BATCH + 63) / 64, 64>>>();
    rescore_kernel<<<BATCH, 256>>>(F);
    ratings_kernel<<<BATCH, 256>>>(F, (float*)d_out);
}

// round 10
// speedup vs baseline: 2.0980x; 2.0980x over previous
#include <cuda_runtime.h>
#include <cuda_bf16.h>
#include <cstdint>

// Problem constants
#define U_ROWS 50000
#define N_ITEMS 4000
#define BATCH 256
#define MAXK 64
#define CAND 32                 // candidates per row, rescored exactly
#define NBLK 391                // GEMM CTAs = ceil(50000/128)
#define PK 8                    // per-(b, CTA) partial top-k

// GEMM config: CTA tile 128(M) x 256(N), BK=32, 3-stage ring (R6 = best known)
#define BK 32
#define KITERS (N_ITEMS / BK)   // 125
#define NTHREADS 512            // 16 warps: 2(M) x 8(N), warp tile 64x32

#define STAGE_BYTES 24576       // A bf16 128x64B (8K) + B bf16 256x64B (16K)
// Csm[128][257] floats = 131584 bytes reuses the stage region post-mainloop
#define OFF_INVNA 131584
#define OFF_INVNU (OFF_INVNA + 512)
#define SMEM_TOTAL (OFF_INVNU + 1024 + 64)

// ---------------- scratch (static device memory) ---------------------------
__device__ __align__(16) float g_users[(size_t)BATCH * N_ITEMS];           // 4 MB fp32
__device__ __align__(16) __nv_bfloat16 g_users_bf[(size_t)BATCH * N_ITEMS];// 2 MB
__device__ __align__(16) unsigned long long g_pk[(size_t)BATCH * NBLK * PK]; // 6.4 MB
__device__ float g_inv_na[U_ROWS];
__device__ float g_inv_nu[BATCH];
__device__ int   g_cand_idx[BATCH * CAND];
__device__ float g_nb_val[BATCH * MAXK];
__device__ int   g_nb_idx[BATCH * MAXK];
__device__ int   g_k;
__device__ int   g_is64;

// ---------------- helpers ---------------------------------------------------
__device__ __forceinline__ uint32_t smem_u32(const void* p) {
    uint32_t a;
    asm("{ .reg .u64 t; cvta.to.shared.u64 t, %1; cvt.u32.u64 %0, t; }" : "=r"(a) : "l"(p));
    return a;
}
#define CP_ASYNC16(dst, src) \
    asm volatile("cp.async.cg.shared.global [%0], [%1], 16;" :: "r"(dst), "l"(src))
#define CP_COMMIT() asm volatile("cp.async.commit_group;" ::: "memory")
#define CP_WAIT(n)  asm volatile("cp.async.wait_group %0;" :: "n"(n) : "memory")

__device__ __forceinline__ float neg_inf() { return __int_as_float(0xFF800000); }
__device__ __forceinline__ unsigned bf16u(float x) {
    return (unsigned)__bfloat16_as_ushort(__float2bfloat16_rn(x));
}
__device__ __forceinline__ uint32_t pack_bf2(float a, float b) {
    uint32_t r;
    asm("cvt.rn.bf16x2.f32 %0, %2, %1;" : "=r"(r) : "f"(a), "f"(b));
    return r;
}
// swizzled chunk byte offset within a 64B-row tile
__device__ __forceinline__ uint32_t swz64(int row, int c) {
    return (uint32_t)(row * 64 + 16 * (c ^ ((row >> 1) & 3)));
}
// order-preserving composite key: (value desc, index asc); key > 0 for v >= 0
__device__ __forceinline__ unsigned long long okey(float v, int idx) {
    unsigned kb = __float_as_uint(v);
    kb ^= (kb >> 31) ? 0xFFFFFFFFu : 0x80000000u;
    return ((unsigned long long)kb << 32) |
           (unsigned long long)(0xFFFFFFFFu - (unsigned)idx);
}
__device__ __forceinline__ int okey_idx(unsigned long long k) {
    return (int)(0xFFFFFFFFu - (unsigned)(k & 0xFFFFFFFFull));
}

// ---------------- kernel 0: dtype/mode + k detection ------------------------
__global__ void mode_kernel(const void* ids, const int* kptr, int has_k) {
    if (threadIdx.x == 0) {
        const unsigned* w = (const unsigned*)ids;
        bool is64 = true;
        for (int i = 0; i < 16; i++)
            if (w[2 * i + 1] != 0u) { is64 = false; break; }
        g_is64 = is64 ? 1 : 0;

        int kk = 10;
        if (has_k) {
            int vi = kptr[0];
            if (vi >= 1 && vi <= MAXK) kk = vi;
            else {
                float vf = __int_as_float(vi);
                if (vf >= 1.f && vf <= (float)MAXK) kk = (int)vf;
            }
        }
        g_k = kk;
    }
}

// ---------------- kernel 1: gather user rows (fp32 + bf16) + exact norms ----
__global__ void gather_users_kernel(const float* __restrict__ F, const void* ids) {
    const int b = blockIdx.x;
    const int tid = threadIdx.x;
    long long uid;
    if (g_is64) uid = ((const long long*)ids)[b];
    else        uid = (long long)((const int*)ids)[b];
    const float4* src = (const float4*)(F + (size_t)uid * N_ITEMS);
    float4* dstf = (float4*)(g_users + (size_t)b * N_ITEMS);
    uint2* dstb = (uint2*)(g_users_bf + (size_t)b * N_ITEMS);
    float s = 0.f;
    for (int v = tid; v < N_ITEMS / 4; v += 256) {
        float4 x = src[v];
        dstf[v] = x;
        uint2 o;
        o.x = bf16u(x.x) | (bf16u(x.y) << 16);
        o.y = bf16u(x.z) | (bf16u(x.w) << 16);
        dstb[v] = o;
        s += x.x * x.x + x.y * x.y + x.z * x.z + x.w * x.w;
    }
    for (int off = 16; off > 0; off >>= 1)
        s += __shfl_down_sync(0xFFFFFFFFu, s, off);
    __shared__ float ws[8];
    if ((tid & 31) == 0) ws[tid >> 5] = s;
    __syncthreads();
    if (tid == 0) {
        float t = 0.f;
        for (int i = 0; i < 8; i++) t += ws[i];
        g_inv_nu[b] = 1.0f / fmaxf(t, 1e-8f);
    }
}

// ---------------- kernel 2: bf16 mma GEMM + fused per-CTA top-PK ------------
__global__ __launch_bounds__(NTHREADS, 1)
void gemm_sim_kernel(const float* __restrict__ F) {
    extern __shared__ __align__(1024) char smem[];
    const uint32_t sbase = smem_u32(smem);
    const int tid = threadIdx.x;
    const int lane = tid & 31;
    const int wid = tid >> 5;
    const int m0 = blockIdx.x * 128;
    const int mw = wid & 1;       // warp M index
    const int nw = wid >> 1;      // warp N index (0..7), warp tile 64x32

    float* invna_s = (float*)(smem + OFF_INVNA);
    float* invnu_s = (float*)(smem + OFF_INVNU);
    if (tid < 256) invnu_s[tid] = g_inv_nu[tid];

    // ---- A producer (fp32 LDG -> cvt -> STS): thread owns (row, 16B chunk) ----
    const int arow = tid >> 2;           // 0..127
    const int ach = tid & 3;             // bf16 16B chunk == fp32 32B chunk
    int gm = m0 + arow; if (gm > U_ROWS - 1) gm = U_ROWS - 1;
    const char* asrc = (const char*)F + (size_t)gm * (N_ITEMS * 4) + ach * 32;
    const uint32_t asts = swz64(arow, ach);

    // ---- B producer (cp.async from bf16 users): rows arow, arow+128 ----
    const char* bsrc0 = (const char*)g_users_bf + (size_t)arow * (N_ITEMS * 2) + ach * 16;
    const char* bsrc1 = bsrc0 + (size_t)128 * (N_ITEMS * 2);
    const uint32_t bst0 = 8192 + swz64(arow, ach);
    const uint32_t bst1 = 8192 + swz64(arow + 128, ach);

    // ---- A fragment (ldmatrix) per-lane constants ----
    const int ahalf = lane >> 4;
    uint32_t a_base[4];
    int a_sw[4];
#pragma unroll
    for (int f = 0; f < 4; f++) {
        int r = mw * 64 + f * 16 + (lane & 15);
        a_base[f] = (uint32_t)(r * 64);
        a_sw[f] = (r >> 1) & 3;
    }
    // ---- B fragment (ldmatrix x4 over 16n x 16k) per-lane constants ----
    const int grp = lane >> 3;
    const int cbit = grp & 1;
    uint32_t b_base[2];
    int b_sw[2];
#pragma unroll
    for (int gp = 0; gp < 2; gp++) {
        int n = nw * 32 + gp * 16 + ((grp & 2) << 2) + (lane & 7);
        b_base[gp] = (uint32_t)(8192 + n * 64);
        b_sw[gp] = (n >> 1) & 3;
    }

    float c[4][4][4];
#pragma unroll
    for (int f = 0; f < 4; f++)
#pragma unroll
        for (int g = 0; g < 4; g++)
#pragma unroll
            for (int i = 0; i < 4; i++) c[f][g][i] = 0.f;

    float ns = 0.f;
    float4 av0, av1;

    auto ldgA = [&](int kt) {
        const char* p = asrc + (size_t)kt * (BK * 4);
        av0 = *(const float4*)p;
        av1 = *(const float4*)(p + 16);
    };
    auto stsA = [&](uint32_t stagebase) {
        ns += av0.x * av0.x + av0.y * av0.y + av0.z * av0.z + av0.w * av0.w;
        ns += av1.x * av1.x + av1.y * av1.y + av1.z * av1.z + av1.w * av1.w;
        uint32_t p0 = pack_bf2(av0.x, av0.y);
        uint32_t p1 = pack_bf2(av0.z, av0.w);
        uint32_t p2 = pack_bf2(av1.x, av1.y);
        uint32_t p3 = pack_bf2(av1.z, av1.w);
        asm volatile("st.shared.v4.b32 [%0], {%1,%2,%3,%4};"
                     :: "r"(stagebase + asts), "r"(p0), "r"(p1), "r"(p2), "r"(p3)
                     : "memory");
    };
    auto issueB = [&](int kt) {
        uint32_t stb = sbase + (kt % 3) * STAGE_BYTES;
        CP_ASYNC16(stb + bst0, bsrc0 + (size_t)kt * (BK * 2));
        CP_ASYNC16(stb + bst1, bsrc1 + (size_t)kt * (BK * 2));
    };

    // ---- prologue ----
    issueB(0); CP_COMMIT();
    issueB(1); CP_COMMIT();
    ldgA(0);
    stsA(sbase);
    ldgA(1);

    // ---- mainloop (R6 best-known) ----
    for (int kt = 0; kt < KITERS; ++kt) {
        CP_WAIT(1);
        __syncthreads();
        if (kt + 2 < KITERS) issueB(kt + 2);
        CP_COMMIT();
        if (kt + 1 < KITERS) stsA(sbase + ((kt + 1) % 3) * STAGE_BYTES);
        if (kt + 2 < KITERS) ldgA(kt + 2);

        const uint32_t stb = sbase + (kt % 3) * STAGE_BYTES;
#pragma unroll
        for (int s = 0; s < 2; ++s) {
            uint32_t af[4][4];
#pragma unroll
            for (int f = 0; f < 4; ++f) {
                uint32_t addr = stb + a_base[f] +
                                (uint32_t)(16 * ((2 * s + ahalf) ^ a_sw[f]));
                asm volatile("ldmatrix.sync.aligned.m8n8.x4.shared.b16 {%0,%1,%2,%3}, [%4];"
                             : "=r"(af[f][0]), "=r"(af[f][1]), "=r"(af[f][2]), "=r"(af[f][3])
                             : "r"(addr));
            }
#pragma unroll
            for (int gp = 0; gp < 2; ++gp) {
                uint32_t bf0, bf1, bf2, bf3;
                uint32_t addr = stb + b_base[gp] +
                                (uint32_t)(16 * ((2 * s + cbit) ^ b_sw[gp]));
                asm volatile("ldmatrix.sync.aligned.m8n8.x4.shared.b16 {%0,%1,%2,%3}, [%4];"
                             : "=r"(bf0), "=r"(bf1), "=r"(bf2), "=r"(bf3)
                             : "r"(addr));
#pragma unroll
                for (int f = 0; f < 4; ++f) {
                    asm volatile(
                        "mma.sync.aligned.m16n8k16.row.col.f32.bf16.bf16.f32 "
                        "{%0,%1,%2,%3}, {%4,%5,%6,%7}, {%8,%9}, {%0,%1,%2,%3};"
                        : "+f"(c[f][2 * gp][0]), "+f"(c[f][2 * gp][1]),
                          "+f"(c[f][2 * gp][2]), "+f"(c[f][2 * gp][3])
                        : "r"(af[f][0]), "r"(af[f][1]), "r"(af[f][2]), "r"(af[f][3]),
                          "r"(bf0), "r"(bf1));
                    asm volatile(
                        "mma.sync.aligned.m16n8k16.row.col.f32.bf16.bf16.f32 "
                        "{%0,%1,%2,%3}, {%4,%5,%6,%7}, {%8,%9}, {%0,%1,%2,%3};"
                        : "+f"(c[f][2 * gp + 1][0]), "+f"(c[f][2 * gp + 1][1]),
                          "+f"(c[f][2 * gp + 1][2]), "+f"(c[f][2 * gp + 1][3])
                        : "r"(af[f][0]), "r"(af[f][1]), "r"(af[f][2]), "r"(af[f][3]),
                          "r"(bf2), "r"(bf3));
                }
            }
        }
    }

    CP_WAIT(0);
    __syncthreads();

    // ---- exact row norms: reduce over the 4 threads sharing a row ----
    {
        float v = ns;
        v += __shfl_xor_sync(0xFFFFFFFFu, v, 1);
        v += __shfl_xor_sync(0xFFFFFFFFu, v, 2);
        if ((tid & 3) == 0) {
            float inv = 1.0f / fmaxf(v, 1e-8f);
            invna_s[arow] = inv;
            if (m0 + arow < U_ROWS) g_inv_na[m0 + arow] = inv;
        }
    }
    __syncthreads();

    // ---- stage scaled sims to Csm[128][257] (reuses stage smem) ----
    float* Csm = (float*)smem;
#pragma unroll
    for (int f = 0; f < 4; ++f) {
        int r0 = mw * 64 + f * 16 + (lane >> 2);
        float na0 = invna_s[r0], na8 = invna_s[r0 + 8];
#pragma unroll
        for (int g = 0; g < 4; ++g) {
            int col = nw * 32 + g * 8 + 2 * (lane & 3);
            float nu0 = invnu_s[col], nu1 = invnu_s[col + 1];
            Csm[r0 * 257 + col]           = c[f][g][0] * na0 * nu0;
            Csm[r0 * 257 + col + 1]       = c[f][g][1] * na0 * nu1;
            Csm[(r0 + 8) * 257 + col]     = c[f][g][2] * na8 * nu0;
            Csm[(r0 + 8) * 257 + col + 1] = c[f][g][3] * na8 * nu1;
        }
    }
    __syncthreads();

    // ---- per-column top-PK over this CTA's 128 rows -> g_pk ----
    if (tid < 256) {
        const int col = tid;
        unsigned long long kk[PK];
#pragma unroll
        for (int j = 0; j < PK; j++) kk[j] = 0ull;

        int rmax = U_ROWS - m0;
        if (rmax > 128) rmax = 128;
        for (int r = 0; r < rmax; ++r) {
            unsigned long long key = okey(Csm[r * 257 + col], m0 + r);
            if (key > kk[PK - 1]) {
                unsigned long long ck = key;
#pragma unroll
                for (int j = 0; j < PK; j++) {
                    if (ck > kk[j]) {
                        unsigned long long t = kk[j];
                        kk[j] = ck; ck = t;
                    }
                }
            }
        }
        unsigned long long* dst = g_pk + ((size_t)col * NBLK + blockIdx.x) * PK;
#pragma unroll
        for (int j = 0; j < PK; j++) dst[j] = kk[j];
    }
}

// ---------------- kernel 3: select top-CAND candidates from partials --------
#define SLOCK 8
__global__ void select_cand_kernel() {
    const int b = blockIdx.x;
    const int tid = threadIdx.x;     // 128 threads
    const int lane = tid & 31;
    const int wid = tid >> 5;

    const unsigned long long* src = g_pk + (size_t)b * NBLK * PK;  // 3128 keys

    unsigned long long kk[SLOCK];
#pragma unroll
    for (int j = 0; j < SLOCK; j++) kk[j] = 0ull;

    for (int i = tid; i < NBLK * PK; i += 128) {
        unsigned long long key = src[i];
        if (key > kk[SLOCK - 1]) {
            unsigned long long ck = key;
#pragma unroll
            for (int j = 0; j < SLOCK; j++) {
                if (ck > kk[j]) {
                    unsigned long long t = kk[j];
                    kk[j] = ck; ck = t;
                }
            }
        }
    }

    __shared__ unsigned long long wbest[4];
    __shared__ int wtid[4];
    __shared__ int swin;

    for (int r = 0; r < CAND; ++r) {
        unsigned long long best = kk[0];
        int bt = tid;
#pragma unroll
        for (int o = 16; o > 0; o >>= 1) {
            unsigned long long ob = __shfl_down_sync(0xFFFFFFFFu, best, o);
            int ot = __shfl_down_sync(0xFFFFFFFFu, bt, o);
            if (ob > best) { best = ob; bt = ot; }
        }
        if (lane == 0) { wbest[wid] = best; wtid[wid] = bt; }
        __syncthreads();
        if (tid == 0) {
            unsigned long long m = wbest[0]; int mt = wtid[0];
            for (int i = 1; i < 4; i++)
                if (wbest[i] > m) { m = wbest[i]; mt = wtid[i]; }
            swin = mt;
        }
        __syncthreads();
        if (tid == swin) {
            g_cand_idx[b * CAND + r] = okey_idx(kk[0]);
#pragma unroll
            for (int j = 0; j < SLOCK - 1; j++) kk[j] = kk[j + 1];
            kk[SLOCK - 1] = 0ull;
        }
        __syncthreads();
    }
}

// ---------------- kernel 4: exact fp32 rescore + top-k ----------------------
__global__ void rescore_kernel(const float* __restrict__ F) {
    const int b = blockIdx.x;
    const int tid = threadIdx.x;
    const int lane = tid & 31;
    const int w = tid >> 5;

    __shared__ float ssim[CAND];
    __shared__ int   sidx[CAND];

    const float* ub = g_users + (size_t)b * N_ITEMS;
    for (int cc = w; cc < CAND; cc += 8) {
        int u = g_cand_idx[b * CAND + cc];
        const float* fu = F + (size_t)u * N_ITEMS;
        float acc = 0.f;
        for (int k = lane; k < N_ITEMS; k += 32)
            acc += ub[k] * fu[k];
        for (int o = 16; o > 0; o >>= 1)
            acc += __shfl_down_sync(0xFFFFFFFFu, acc, o);
        if (lane == 0) {
            ssim[cc] = acc * g_inv_na[u] * g_inv_nu[b];
            sidx[cc] = u;
        }
    }
    __syncthreads();

    if (tid == 0) {
        int k = g_k < CAND ? g_k : CAND;
        bool used[CAND];
        for (int i = 0; i < CAND; i++) used[i] = false;
        for (int r = 0; r < k; r++) {
            int bi = -1;
            float bv = neg_inf();
            int bidx = 0x7FFFFFFF;
            for (int cc = 0; cc < CAND; cc++) {
                if (used[cc]) continue;
                float v = ssim[cc];
                if (v > bv || (v == bv && sidx[cc] < bidx)) {
                    bv = v; bidx = sidx[cc]; bi = cc;
                }
            }
            used[bi] = true;
            g_nb_val[b * MAXK + r] = bv;
            g_nb_idx[b * MAXK + r] = bidx;
        }
    }
}

// ---------------- kernel 5: weighted neighbor gather ------------------------
__global__ void ratings_kernel(const float* __restrict__ F, float* __restrict__ out) {
    const int b = blockIdx.x;
    const int tid = threadIdx.x;
    const int k = g_k < CAND ? g_k : CAND;

    __shared__ float w[MAXK];
    __shared__ int   id[MAXK];
    if (tid == 0) {
        float s = 0.f;
        for (int j = 0; j < k; j++) s += g_nb_val[b * MAXK + j];
        float inv = 1.0f / s;
        for (int j = 0; j < k; j++) {
            w[j]  = g_nb_val[b * MAXK + j] * inv;
            id[j] = g_nb_idx[b * MAXK + j];
        }
    }
    __syncthreads();

    for (int i = tid; i < N_ITEMS; i += 256) {
        float acc = 0.f;
        for (int j = 0; j < k; j++)
            acc += w[j] * F[(size_t)id[j] * N_ITEMS + i];
        out[(size_t)b * N_ITEMS + i] = acc;
    }
}

// ---------------- launch ----------------------------------------------------
extern "C" void kernel_launch(void* const* d_in, const int* in_sizes, int n_in,
                              void* d_out, int out_size) {
    const float* F = (const float*)d_in[0];
    const void* ids = d_in[1];
    const int* kptr = (n_in > 2) ? (const int*)d_in[2] : nullptr;

    cudaFuncSetAttribute(gemm_sim_kernel,
                         cudaFuncAttributeMaxDynamicSharedMemorySize, SMEM_TOTAL);

    mode_kernel<<<1, 32>>>(ids, kptr, kptr != nullptr ? 1 : 0);
    gather_users_kernel<<<BATCH, 256>>>(F, ids);

    gemm_sim_kernel<<<NBLK, NTHREADS, SMEM_TOTAL>>>(F);

    select_cand_kernel<<<BATCH, 128>>>();
    rescore_kernel<<<BATCH, 256>>>(F);
    ratings_kernel<<<BATCH, 256>>>(F, (float*)d_out);
}